// round 14
// baseline (speedup 1.0000x reference)
#include <cuda_runtime.h>
#include <cstdint>
#include <math.h>

#define NPIX 41472      // 8*72*72
#define TT 64

// ---------------- device scratch (no allocations allowed) ----------------
__device__ float g_perc[2][NPIX * 48];   // double-buffered (stream overlap WAR)
__device__ float g_h[NPIX * 16];
__device__ float g_lam[2 * NPIX];
__device__ float g_un[NPIX];
__device__ float g_pre[NPIX];
__device__ float g_xcur[NPIX * 16];
__device__ float g_xn[NPIX * 16];

// ---------------- threefry-2x32 (JAX-compatible) ----------------
__device__ __forceinline__ uint2 d_threefry(uint32_t k0, uint32_t k1,
                                            uint32_t x0, uint32_t x1) {
    uint32_t ks2 = k0 ^ k1 ^ 0x1BD11BDAu;
    x0 += k0; x1 += k1;
#define TFR(r) { x0 += x1; x1 = __funnelshift_l(x1, x1, (r)); x1 ^= x0; }
    TFR(13) TFR(15) TFR(26) TFR(6)  x0 += k1;  x1 += ks2 + 1u;
    TFR(17) TFR(29) TFR(16) TFR(24) x0 += ks2; x1 += k0 + 2u;
    TFR(13) TFR(15) TFR(26) TFR(6)  x0 += k0;  x1 += k1 + 3u;
    TFR(17) TFR(29) TFR(16) TFR(24) x0 += k1;  x1 += ks2 + 4u;
    TFR(13) TFR(15) TFR(26) TFR(6)  x0 += ks2; x1 += k0 + 5u;
#undef TFR
    return make_uint2(x0, x1);
}

static void h_threefry(uint32_t k0, uint32_t k1, uint32_t x0, uint32_t x1,
                       uint32_t* o0, uint32_t* o1) {
    uint32_t ks2 = k0 ^ k1 ^ 0x1BD11BDAu;
    x0 += k0; x1 += k1;
    const int ra[4] = {13, 15, 26, 6}, rb[4] = {17, 29, 16, 24};
    uint32_t ks[3] = {k0, k1, ks2};
    for (int i = 0; i < 5; i++) {
        const int* rr = (i & 1) ? rb : ra;
        for (int r = 0; r < 4; r++) {
            x0 += x1;
            x1 = (x1 << rr[r]) | (x1 >> (32 - rr[r]));
            x1 ^= x0;
        }
        x0 += ks[(i + 1) % 3];
        x1 += ks[(i + 2) % 3] + (uint32_t)(i + 1);
    }
    *o0 = x0; *o1 = x1;
}

// ---------------- perceive: x -> [x, sobel1, sobel2] (48 ch), float4 ----------------
__global__ void k_perc(const float* __restrict__ xext, int use_ext, int psel) {
    const float* __restrict__ x = use_ext ? xext : g_xcur;
    float* __restrict__ gp = g_perc[psel];
    int t = blockIdx.x * 256 + threadIdx.x;   // NPIX*4 threads
    int p = t >> 2, c4 = (t & 3) * 4;
    int b = p / 5184; int hw = p - b * 5184;
    int h = hw / 72, w = hw - h * 72;

    const float W1[3][3] = {{-0.125f, -0.25f, -0.125f},
                            { 0.f,     0.f,    0.f   },
                            { 0.125f,  0.25f,  0.125f}};
    const float W2[3][3] = {{-0.125f, 0.f, 0.125f},
                            {-0.25f,  0.f, 0.25f },
                            {-0.125f, 0.f, 0.125f}};
    float4 ctr = *(const float4*)&x[(p << 4) + c4];
    float4 s1 = make_float4(0.f, 0.f, 0.f, 0.f);
    float4 s2 = make_float4(0.f, 0.f, 0.f, 0.f);
#pragma unroll
    for (int i = 0; i < 3; i++) {
        int hh = h + i - 1;
        if ((unsigned)hh >= 72u) continue;
#pragma unroll
        for (int j = 0; j < 3; j++) {
            int ww = w + j - 1;
            if ((unsigned)ww >= 72u) continue;
            float4 v = *(const float4*)&x[((b * 5184 + hh * 72 + ww) << 4) + c4];
            float w1 = W1[i][j], w2 = W2[i][j];
            s1.x = fmaf(v.x, w1, s1.x); s1.y = fmaf(v.y, w1, s1.y);
            s1.z = fmaf(v.z, w1, s1.z); s1.w = fmaf(v.w, w1, s1.w);
            s2.x = fmaf(v.x, w2, s2.x); s2.y = fmaf(v.y, w2, s2.y);
            s2.z = fmaf(v.z, w2, s2.z); s2.w = fmaf(v.w, w2, s2.w);
        }
    }
    int base = p * 48 + c4;
    *(float4*)&gp[base]      = ctr;
    *(float4*)&gp[base + 16] = s1;
    *(float4*)&gp[base + 32] = s2;
}

// ---------------- conv1: 216 pixels (3 rows) / block, smem 69120 B ----------------
__global__ void __launch_bounds__(256, 2) k_c1(
    int psel, const float* __restrict__ c1w, const float* __restrict__ c1b)
{
    extern __shared__ float sm[];
    int t = threadIdx.x;
    const float* __restrict__ gp = g_perc[psel];

    int bk = blockIdx.x;
    int img = bk / 24, chunk = bk - img * 24;
    int r0 = chunk * 3;
    int pbase = img * 5184 + r0 * 72;

    float* s_p = sm;                    // [5][72][48], rows r0-1..r0+3, zero-padded
    for (int i = t; i < 4320; i += 256) {
        int row = i / 864;
        int rem = i - row * 864;
        int pix = rem / 12;
        int c4 = (rem - pix * 12) * 4;
        int gr = r0 - 1 + row;
        float4 v = make_float4(0.f, 0.f, 0.f, 0.f);
        if ((unsigned)gr < 72u)
            v = *(const float4*)&gp[(img * 5184 + gr * 72 + pix) * 48 + c4];
        *(float4*)&s_p[(row * 72 + pix) * 48 + c4] = v;
    }
    __syncthreads();

    if (t < 216) {
        int og = t & 3, pg = t >> 2;        // pg 0..53
        int o0 = og * 4;
        int lr = pg / 18;                   // local out row 0..2
        int c0 = (pg - lr * 18) * 4;        // starting col, multiple of 4

        float4 b4 = __ldg((const float4*)&c1b[o0]);
        float acc[4][4];
#pragma unroll
        for (int s = 0; s < 4; s++) {
            acc[s][0] = b4.x; acc[s][1] = b4.y;
            acc[s][2] = b4.z; acc[s][3] = b4.w;
        }

        for (int i = 0; i < 3; i++) {
            const float* __restrict__ prow = &s_p[(lr + i) * 72 * 48];
#pragma unroll
            for (int j = 0; j < 3; j++) {
                int wbase = c0 + j - 1;
                const float4* __restrict__ wp =
                    (const float4*)(c1w + (i * 3 + j) * 768 + o0);
#pragma unroll 4
                for (int c4i = 0; c4i < 12; c4i++) {
                    float4 wv0 = __ldg(&wp[(c4i * 4 + 0) * 4]);
                    float4 wv1 = __ldg(&wp[(c4i * 4 + 1) * 4]);
                    float4 wv2 = __ldg(&wp[(c4i * 4 + 2) * 4]);
                    float4 wv3 = __ldg(&wp[(c4i * 4 + 3) * 4]);
#pragma unroll
                    for (int s = 0; s < 4; s++) {
                        int ww = wbase + s;
                        if ((unsigned)ww < 72u) {
                            float4 pv = *(const float4*)&prow[ww * 48 + c4i * 4];
                            acc[s][0] = fmaf(pv.x, wv0.x, acc[s][0]);
                            acc[s][1] = fmaf(pv.x, wv0.y, acc[s][1]);
                            acc[s][2] = fmaf(pv.x, wv0.z, acc[s][2]);
                            acc[s][3] = fmaf(pv.x, wv0.w, acc[s][3]);
                            acc[s][0] = fmaf(pv.y, wv1.x, acc[s][0]);
                            acc[s][1] = fmaf(pv.y, wv1.y, acc[s][1]);
                            acc[s][2] = fmaf(pv.y, wv1.z, acc[s][2]);
                            acc[s][3] = fmaf(pv.y, wv1.w, acc[s][3]);
                            acc[s][0] = fmaf(pv.z, wv2.x, acc[s][0]);
                            acc[s][1] = fmaf(pv.z, wv2.y, acc[s][1]);
                            acc[s][2] = fmaf(pv.z, wv2.z, acc[s][2]);
                            acc[s][3] = fmaf(pv.z, wv2.w, acc[s][3]);
                            acc[s][0] = fmaf(pv.w, wv3.x, acc[s][0]);
                            acc[s][1] = fmaf(pv.w, wv3.y, acc[s][1]);
                            acc[s][2] = fmaf(pv.w, wv3.z, acc[s][2]);
                            acc[s][3] = fmaf(pv.w, wv3.w, acc[s][3]);
                        }
                    }
                }
            }
        }
#pragma unroll
        for (int s = 0; s < 4; s++) {
            float4 o = make_float4(fmaxf(acc[s][0], 0.f), fmaxf(acc[s][1], 0.f),
                                   fmaxf(acc[s][2], 0.f), fmaxf(acc[s][3], 0.f));
            *(float4*)&g_h[(pbase + pg * 4 + s) * 16 + o0] = o;
        }
    }
}

// ------- update: 144 pixels / block, 384 threads, grid 288 (single wave) -------
// phase1: s_pT[48][144] (27648 B)
// phase2: s_h[144][132] (76032 B, overlays s_pT) | s_dx[144][16] (9216 B)
// total = 85248 B; 2 blocks/SM (170496 <= 228K), 288 blocks <= 296 capacity
#define UPD_SMEM 85248

__global__ void __launch_bounds__(384, 2) k_upd(
    const float* __restrict__ xext, int use_ext, int psel,
    const float* __restrict__ f0w, const float* __restrict__ f0b,
    const float* __restrict__ f1w,
    float* __restrict__ upd_slot, int rsel, uint32_t key0, uint32_t key1)
{
    extern __shared__ float sm[];
    int t = threadIdx.x;
    const float* __restrict__ gp = g_perc[psel];
    int P0 = (int)blockIdx.x * 144;

    float* s_pT = sm;                   // [48][144] during phase 1
    float* s_h  = sm;                   // [144][132] phase 2 (overlays s_pT)
    float* s_dx = sm + 19008;           // [144][16]

    for (int i = t; i < 1728; i += 384) {          // 144 pix * 12 c4-groups
        int pix = i / 12, c4 = (i - pix * 12) * 4;
        float4 v = *(const float4*)&gp[(P0 + pix) * 48 + c4];
        s_pT[(c4 + 0) * 144 + pix] = v.x;
        s_pT[(c4 + 1) * 144 + pix] = v.y;
        s_pT[(c4 + 2) * 144 + pix] = v.z;
        s_pT[(c4 + 3) * 144 + pix] = v.w;
    }
    __syncthreads();

    // GEMM1: h[144 pix][128 e] = perc[144][48] @ f0[48][128] + b, relu
    // thread tile: 6 pixels x 8 e (48 accumulators); tx 0..15, ty 0..23
    int tx = t & 15, ty = t >> 4;
    int e0 = tx * 8, p0 = ty * 6;
    float acc[6][8];
#pragma unroll
    for (int j = 0; j < 8; j++) {
        float bj = __ldg(&f0b[e0 + j]);
#pragma unroll
        for (int i = 0; i < 6; i++) acc[i][j] = bj;
    }

#pragma unroll 4
    for (int k = 0; k < 48; k++) {
        float2 pa = *(const float2*)&s_pT[k * 144 + p0];       // 24B-aligned base
        float2 pb = *(const float2*)&s_pT[k * 144 + p0 + 2];
        float2 pc = *(const float2*)&s_pT[k * 144 + p0 + 4];
        float4 wa = __ldg((const float4*)&f0w[k * 128 + e0]);
        float4 wb = __ldg((const float4*)&f0w[k * 128 + e0 + 4]);
        float pr[6] = {pa.x, pa.y, pb.x, pb.y, pc.x, pc.y};
        float wr[8] = {wa.x, wa.y, wa.z, wa.w, wb.x, wb.y, wb.z, wb.w};
#pragma unroll
        for (int i = 0; i < 6; i++)
#pragma unroll
            for (int j = 0; j < 8; j++)
                acc[i][j] = fmaf(pr[i], wr[j], acc[i][j]);
    }
    __syncthreads();   // all s_pT reads done before s_h overlays it

#pragma unroll
    for (int i = 0; i < 6; i++) {
        float4 ha = make_float4(fmaxf(acc[i][0], 0.f), fmaxf(acc[i][1], 0.f),
                                fmaxf(acc[i][2], 0.f), fmaxf(acc[i][3], 0.f));
        float4 hb = make_float4(fmaxf(acc[i][4], 0.f), fmaxf(acc[i][5], 0.f),
                                fmaxf(acc[i][6], 0.f), fmaxf(acc[i][7], 0.f));
        *(float4*)&s_h[(p0 + i) * 132 + e0]     = ha;
        *(float4*)&s_h[(p0 + i) * 132 + e0 + 4] = hb;
    }
    __syncthreads();

    // GEMM2: dx[144][16] = h[144][128] @ f1[128][16]; threads 0..287: 1 pix x 8 outs
    if (t < 288) {
        int pix = t >> 1, oo = (t & 1) * 8;
        float d[8];
#pragma unroll
        for (int j = 0; j < 8; j++) d[j] = 0.f;
#pragma unroll 4
        for (int k4 = 0; k4 < 32; k4++) {
            float4 hv4 = *(const float4*)&s_h[pix * 132 + k4 * 4];
            float hr[4] = {hv4.x, hv4.y, hv4.z, hv4.w};
#pragma unroll
            for (int kk = 0; kk < 4; kk++) {
                int k = k4 * 4 + kk;
                float4 w0 = __ldg((const float4*)&f1w[k * 16 + oo]);
                float4 w1 = __ldg((const float4*)&f1w[k * 16 + oo + 4]);
                float hv = hr[kk];
                d[0] = fmaf(hv, w0.x, d[0]);
                d[1] = fmaf(hv, w0.y, d[1]);
                d[2] = fmaf(hv, w0.z, d[2]);
                d[3] = fmaf(hv, w0.w, d[3]);
                d[4] = fmaf(hv, w1.x, d[4]);
                d[5] = fmaf(hv, w1.y, d[5]);
                d[6] = fmaf(hv, w1.z, d[6]);
                d[7] = fmaf(hv, w1.w, d[7]);
            }
        }
        *(float4*)&s_dx[pix * 16 + oo]     = make_float4(d[0], d[1], d[2], d[3]);
        *(float4*)&s_dx[pix * 16 + oo + 4] = make_float4(d[4], d[5], d[6], d[7]);
    }
    __syncthreads();

    if (t < 144) {
        const float* __restrict__ x = use_ext ? xext : g_xcur;
        int gp2 = P0 + t;
        uint2 r = d_threefry(key0, key1, 0u, (uint32_t)gp2);
        uint32_t bits = r.x ^ r.y;
        float u = __uint_as_float((bits >> 9) | 0x3f800000u) - 1.0f;
        float lam = g_lam[rsel * NPIX + gp2];
        float updf = (u < lam) ? 0.0f : 1.0f;

        int b = gp2 / 5184; int hw = gp2 - b * 5184;
        int h = hw / 72, w = hw - h * 72;
        float m = -3.4e38f;
#pragma unroll
        for (int i = 0; i < 3; i++) {
            int hh = h + i - 1;
            if ((unsigned)hh >= 72u) continue;
#pragma unroll
            for (int j = 0; j < 3; j++) {
                int ww = w + j - 1;
                if ((unsigned)ww >= 72u) continue;
                m = fmaxf(m, x[((b * 5184 + hh * 72 + ww) << 4) + 3]);
            }
        }
        g_pre[gp2] = (m > 0.1f) ? 1.f : 0.f;
        upd_slot[gp2] = updf;

        const float4* __restrict__ xr = (const float4*)(x + (gp2 << 4));
        float4* __restrict__ xo = (float4*)(g_xn + (gp2 << 4));
#pragma unroll
        for (int q = 0; q < 4; q++) {
            float4 xv = xr[q];
            float4 dv = *(const float4*)&s_dx[t * 16 + q * 4];
            xv.x = fmaf(dv.x, updf, xv.x);
            xv.y = fmaf(dv.y, updf, xv.y);
            xv.z = fmaf(dv.z, updf, xv.z);
            xv.w = fmaf(dv.w, updf, xv.w);
            xo[q] = xv;
        }
    }
}

// ---------------- conv2 + lambda/p/un bookkeeping (162 blocks) ----------------
__global__ void k_c2(const float* __restrict__ w2, const float* __restrict__ b2,
                     float* __restrict__ lam_slot, float* __restrict__ p_slot,
                     int wsel, int is_first)
{
    __shared__ float ws[144];
    if (threadIdx.x < 144) ws[threadIdx.x] = w2[threadIdx.x];
    __syncthreads();

    int p = blockIdx.x * 256 + threadIdx.x;
    int b = p / 5184; int hw = p - b * 5184;
    int h = hw / 72, w = hw - h * 72;

    float acc = b2[0];
#pragma unroll
    for (int i = 0; i < 3; i++) {
        int hh = h + i - 1;
        if ((unsigned)hh >= 72u) continue;
#pragma unroll
        for (int j = 0; j < 3; j++) {
            int ww = w + j - 1;
            if ((unsigned)ww >= 72u) continue;
            const float4* __restrict__ hp =
                (const float4*)&g_h[(b * 5184 + hh * 72 + ww) << 4];
            const float* __restrict__ wp = ws + (i * 3 + j) * 16;
#pragma unroll
            for (int q = 0; q < 4; q++) {
                float4 hv = hp[q];
                acc = fmaf(hv.x, wp[q * 4 + 0], acc);
                acc = fmaf(hv.y, wp[q * 4 + 1], acc);
                acc = fmaf(hv.z, wp[q * 4 + 2], acc);
                acc = fmaf(hv.w, wp[q * 4 + 3], acc);
            }
        }
    }
    float lam = 1.f / (1.f + expf(-acc));
    g_lam[wsel * NPIX + p] = lam;
    float un = is_first ? 1.0f : g_un[p];
    lam_slot[p] = lam;
    p_slot[p] = un * lam + 1e-6f;
    g_un[p] = un * (1.f - lam);
}

// ---------------- life mask + x_steps emit (162 blocks) ----------------
__global__ void k_life(float* __restrict__ xsteps_slot)
{
    int p = blockIdx.x * 256 + threadIdx.x;
    int b = p / 5184; int hw = p - b * 5184;
    int h = hw / 72, w = hw - h * 72;
    float m = -3.4e38f;
#pragma unroll
    for (int i = 0; i < 3; i++) {
        int hh = h + i - 1;
        if ((unsigned)hh >= 72u) continue;
#pragma unroll
        for (int j = 0; j < 3; j++) {
            int ww = w + j - 1;
            if ((unsigned)ww >= 72u) continue;
            m = fmaxf(m, g_xn[((b * 5184 + hh * 72 + ww) << 4) + 3]);
        }
    }
    float life = ((m > 0.1f) && (g_pre[p] != 0.f)) ? 1.f : 0.f;
    const float4* __restrict__ xi = (const float4*)(g_xn + (p << 4));
    float4* __restrict__ xc = (float4*)(g_xcur + (p << 4));
    float4* __restrict__ xs = (float4*)(xsteps_slot + (p << 4));
#pragma unroll
    for (int q = 0; q < 4; q++) {
        float4 v = xi[q];
        v.x *= life; v.y *= life; v.z *= life; v.w *= life;
        xc[q] = v;
        xs[q] = v;
    }
}

// ------- normalize p over the T axis (in-place in output region) -------
__global__ void k_pnorm(float* __restrict__ pbase) {
    int p = blockIdx.x * 256 + threadIdx.x;
    float s = 0.f;
#pragma unroll 8
    for (int t = 0; t < TT; t++) s += pbase[t * NPIX + p];
#pragma unroll 8
    for (int t = 0; t < TT; t++) pbase[t * NPIX + p] = pbase[t * NPIX + p] / s;
}

// ---------------- launch ----------------
extern "C" void kernel_launch(void* const* d_in, const int* in_sizes, int n_in,
                              void* d_out, int out_size) {
    (void)in_sizes; (void)n_in; (void)out_size;
    const float* x   = (const float*)d_in[0];
    const float* c1w = (const float*)d_in[1];
    const float* c1b = (const float*)d_in[2];
    const float* c2w = (const float*)d_in[3];
    const float* c2b = (const float*)d_in[4];
    const float* f0w = (const float*)d_in[5];
    const float* f0b = (const float*)d_in[6];
    const float* f1w = (const float*)d_in[7];

    float* out    = (float*)d_out;
    float* xsteps = out;                                  // (64, NPIX, 16)
    float* pout   = out + (size_t)TT * NPIX * 16;         // (64, NPIX)
    float* lamout = pout + (size_t)TT * NPIX;             // (64, NPIX)
    float* updout = lamout + (size_t)TT * NPIX;           // (64, NPIX)

    static cudaStream_t sB;
    static cudaEvent_t evA, evB;
    static int inited = 0;
    if (!inited) {
        cudaFuncSetAttribute(k_c1,  cudaFuncAttributeMaxDynamicSharedMemorySize, 69120);
        cudaFuncSetAttribute(k_upd, cudaFuncAttributeMaxDynamicSharedMemorySize, UPD_SMEM);
        cudaStreamCreateWithFlags(&sB, cudaStreamNonBlocking);
        cudaEventCreateWithFlags(&evA, cudaEventDisableTiming);
        cudaEventCreateWithFlags(&evB, cudaEventDisableTiming);
        inited = 1;
    }

    // per-step keys: fold_in(key(42), k) = threefry((0,42),(0,k))
    uint32_t kk0[TT], kk1[TT];
    for (int n = 0; n < TT; n++) h_threefry(0u, 42u, 0u, (uint32_t)n, &kk0[n], &kk1[n]);

    // ---- step 0: update depends on THIS step's lambda -> strict serial order ----
    k_perc<<<648, 256>>>(x, 1, 0);
    k_c1<<<192, 256, 69120>>>(0, c1w, c1b);
    k_c2<<<162, 256>>>(c2w, c2b, lamout, pout, 0, 1);
    k_upd<<<288, 384, UPD_SMEM>>>(x, 1, 0, f0w, f0b, f1w, updout, 0, kk0[0], kk1[0]);
    k_life<<<162, 256>>>(xsteps);

    // ---- steps 1..63: (c1 -> c2) side chain overlapped on stream sB ----
    for (int k = 1; k < TT; k++) {
        int wsel = k & 1;
        int rsel = (k - 1) & 1;
        int psel = k & 1;

        // main chain: perc_k (after life_{k-1} by stream order)
        k_perc<<<648, 256>>>(x, 0, psel);
        cudaEventRecord(evA, 0);
        cudaStreamWaitEvent(sB, evA, 0);

        // main chain must wait on c2_{k-1} (lambda slot rsel) — wait BEFORE
        // re-recording evB below so it references the previous record.
        if (k >= 2) cudaStreamWaitEvent(0, evB, 0);

        // side chain: c1_k -> c2_k on sB
        k_c1<<<192, 256, 69120, sB>>>(psel, c1w, c1b);
        k_c2<<<162, 256, 0, sB>>>(c2w, c2b,
                                  lamout + (size_t)k * NPIX, pout + (size_t)k * NPIX,
                                  wsel, 0);
        cudaEventRecord(evB, sB);

        // main chain: upd_k -> life_k
        k_upd<<<288, 384, UPD_SMEM>>>(x, 0, psel, f0w, f0b, f1w,
                                      updout + (size_t)k * NPIX, rsel, kk0[k], kk1[k]);
        k_life<<<162, 256>>>(xsteps + (size_t)k * NPIX * 16);
    }

    // join side chain (c2_63 writes pout[63]) before normalization
    cudaStreamWaitEvent(0, evB, 0);
    k_pnorm<<<162, 256>>>(pout);
}

// round 15
// speedup vs baseline: 1.2463x; 1.2463x over previous
#include <cuda_runtime.h>
#include <cstdint>
#include <math.h>

#define NPIX 41472      // 8*72*72
#define TT 64

// ---------------- device scratch (no allocations allowed) ----------------
__device__ float g_perc[2][NPIX * 48];   // double-buffered (stream overlap WAR)
__device__ float g_h[NPIX * 16];
__device__ float g_lam[2 * NPIX];
__device__ float g_un[NPIX];
__device__ float g_pre[NPIX];
__device__ float g_xcur[NPIX * 16];
__device__ float g_xn[NPIX * 16];

// ---------------- threefry-2x32 (JAX-compatible) ----------------
__device__ __forceinline__ uint2 d_threefry(uint32_t k0, uint32_t k1,
                                            uint32_t x0, uint32_t x1) {
    uint32_t ks2 = k0 ^ k1 ^ 0x1BD11BDAu;
    x0 += k0; x1 += k1;
#define TFR(r) { x0 += x1; x1 = __funnelshift_l(x1, x1, (r)); x1 ^= x0; }
    TFR(13) TFR(15) TFR(26) TFR(6)  x0 += k1;  x1 += ks2 + 1u;
    TFR(17) TFR(29) TFR(16) TFR(24) x0 += ks2; x1 += k0 + 2u;
    TFR(13) TFR(15) TFR(26) TFR(6)  x0 += k0;  x1 += k1 + 3u;
    TFR(17) TFR(29) TFR(16) TFR(24) x0 += k1;  x1 += ks2 + 4u;
    TFR(13) TFR(15) TFR(26) TFR(6)  x0 += ks2; x1 += k0 + 5u;
#undef TFR
    return make_uint2(x0, x1);
}

static void h_threefry(uint32_t k0, uint32_t k1, uint32_t x0, uint32_t x1,
                       uint32_t* o0, uint32_t* o1) {
    uint32_t ks2 = k0 ^ k1 ^ 0x1BD11BDAu;
    x0 += k0; x1 += k1;
    const int ra[4] = {13, 15, 26, 6}, rb[4] = {17, 29, 16, 24};
    uint32_t ks[3] = {k0, k1, ks2};
    for (int i = 0; i < 5; i++) {
        const int* rr = (i & 1) ? rb : ra;
        for (int r = 0; r < 4; r++) {
            x0 += x1;
            x1 = (x1 << rr[r]) | (x1 >> (32 - rr[r]));
            x1 ^= x0;
        }
        x0 += ks[(i + 1) % 3];
        x1 += ks[(i + 2) % 3] + (uint32_t)(i + 1);
    }
    *o0 = x0; *o1 = x1;
}

// ---------------- perceive: x -> [x, sobel1, sobel2] (48 ch), float4 ----------------
__global__ void k_perc(const float* __restrict__ xext, int use_ext, int psel) {
    const float* __restrict__ x = use_ext ? xext : g_xcur;
    float* __restrict__ gp = g_perc[psel];
    int t = blockIdx.x * 256 + threadIdx.x;   // NPIX*4 threads
    int p = t >> 2, c4 = (t & 3) * 4;
    int b = p / 5184; int hw = p - b * 5184;
    int h = hw / 72, w = hw - h * 72;

    const float W1[3][3] = {{-0.125f, -0.25f, -0.125f},
                            { 0.f,     0.f,    0.f   },
                            { 0.125f,  0.25f,  0.125f}};
    const float W2[3][3] = {{-0.125f, 0.f, 0.125f},
                            {-0.25f,  0.f, 0.25f },
                            {-0.125f, 0.f, 0.125f}};
    float4 ctr = *(const float4*)&x[(p << 4) + c4];
    float4 s1 = make_float4(0.f, 0.f, 0.f, 0.f);
    float4 s2 = make_float4(0.f, 0.f, 0.f, 0.f);
#pragma unroll
    for (int i = 0; i < 3; i++) {
        int hh = h + i - 1;
        if ((unsigned)hh >= 72u) continue;
#pragma unroll
        for (int j = 0; j < 3; j++) {
            int ww = w + j - 1;
            if ((unsigned)ww >= 72u) continue;
            float4 v = *(const float4*)&x[((b * 5184 + hh * 72 + ww) << 4) + c4];
            float w1 = W1[i][j], w2 = W2[i][j];
            s1.x = fmaf(v.x, w1, s1.x); s1.y = fmaf(v.y, w1, s1.y);
            s1.z = fmaf(v.z, w1, s1.z); s1.w = fmaf(v.w, w1, s1.w);
            s2.x = fmaf(v.x, w2, s2.x); s2.y = fmaf(v.y, w2, s2.y);
            s2.z = fmaf(v.z, w2, s2.z); s2.w = fmaf(v.w, w2, s2.w);
        }
    }
    int base = p * 48 + c4;
    *(float4*)&gp[base]      = ctr;
    *(float4*)&gp[base + 16] = s1;
    *(float4*)&gp[base + 32] = s2;
}

// ------- conv1: 216 pixels (3 rows) / block, s_p[5][72][52] = 74880 B -------
#define C1_SMEM 74880

__global__ void __launch_bounds__(256, 2) k_c1(
    int psel, const float* __restrict__ c1w, const float* __restrict__ c1b)
{
    extern __shared__ float sm[];
    int t = threadIdx.x;
    const float* __restrict__ gp = g_perc[psel];

    int bk = blockIdx.x;
    int img = bk / 24, chunk = bk - img * 24;
    int r0 = chunk * 3;
    int pbase = img * 5184 + r0 * 72;

    float* s_p = sm;                    // [5][72] rows, 52-float stride (conflict-free)
    for (int i = t; i < 4320; i += 256) {
        int row = i / 864;
        int rem = i - row * 864;
        int pix = rem / 12;
        int c4 = (rem - pix * 12) * 4;
        int gr = r0 - 1 + row;
        float4 v = make_float4(0.f, 0.f, 0.f, 0.f);
        if ((unsigned)gr < 72u)
            v = *(const float4*)&gp[(img * 5184 + gr * 72 + pix) * 48 + c4];
        *(float4*)&s_p[(row * 72 + pix) * 52 + c4] = v;
    }
    __syncthreads();

    if (t < 216) {
        int og = t & 3, pg = t >> 2;        // pg 0..53
        int o0 = og * 4;
        int lr = pg / 18;                   // local out row 0..2
        int c0 = (pg - lr * 18) * 4;        // starting col, multiple of 4

        float4 b4 = __ldg((const float4*)&c1b[o0]);
        float acc[4][4];
#pragma unroll
        for (int s = 0; s < 4; s++) {
            acc[s][0] = b4.x; acc[s][1] = b4.y;
            acc[s][2] = b4.z; acc[s][3] = b4.w;
        }

        for (int i = 0; i < 3; i++) {
            const float* __restrict__ prow = &s_p[(lr + i) * 72 * 52];
#pragma unroll
            for (int j = 0; j < 3; j++) {
                int wbase = c0 + j - 1;
                const float4* __restrict__ wp =
                    (const float4*)(c1w + (i * 3 + j) * 768 + o0);
#pragma unroll 4
                for (int c4i = 0; c4i < 12; c4i++) {
                    float4 wv0 = __ldg(&wp[(c4i * 4 + 0) * 4]);
                    float4 wv1 = __ldg(&wp[(c4i * 4 + 1) * 4]);
                    float4 wv2 = __ldg(&wp[(c4i * 4 + 2) * 4]);
                    float4 wv3 = __ldg(&wp[(c4i * 4 + 3) * 4]);
#pragma unroll
                    for (int s = 0; s < 4; s++) {
                        int ww = wbase + s;
                        if ((unsigned)ww < 72u) {
                            float4 pv = *(const float4*)&prow[ww * 52 + c4i * 4];
                            acc[s][0] = fmaf(pv.x, wv0.x, acc[s][0]);
                            acc[s][1] = fmaf(pv.x, wv0.y, acc[s][1]);
                            acc[s][2] = fmaf(pv.x, wv0.z, acc[s][2]);
                            acc[s][3] = fmaf(pv.x, wv0.w, acc[s][3]);
                            acc[s][0] = fmaf(pv.y, wv1.x, acc[s][0]);
                            acc[s][1] = fmaf(pv.y, wv1.y, acc[s][1]);
                            acc[s][2] = fmaf(pv.y, wv1.z, acc[s][2]);
                            acc[s][3] = fmaf(pv.y, wv1.w, acc[s][3]);
                            acc[s][0] = fmaf(pv.z, wv2.x, acc[s][0]);
                            acc[s][1] = fmaf(pv.z, wv2.y, acc[s][1]);
                            acc[s][2] = fmaf(pv.z, wv2.z, acc[s][2]);
                            acc[s][3] = fmaf(pv.z, wv2.w, acc[s][3]);
                            acc[s][0] = fmaf(pv.w, wv3.x, acc[s][0]);
                            acc[s][1] = fmaf(pv.w, wv3.y, acc[s][1]);
                            acc[s][2] = fmaf(pv.w, wv3.z, acc[s][2]);
                            acc[s][3] = fmaf(pv.w, wv3.w, acc[s][3]);
                        }
                    }
                }
            }
        }
#pragma unroll
        for (int s = 0; s < 4; s++) {
            float4 o = make_float4(fmaxf(acc[s][0], 0.f), fmaxf(acc[s][1], 0.f),
                                   fmaxf(acc[s][2], 0.f), fmaxf(acc[s][3], 0.f));
            *(float4*)&g_h[(pbase + pg * 4 + s) * 16 + o0] = o;
        }
    }
}

// ------- update: 128 pixels / block, 256 threads, grid 324 -------
// phase1: s_p[128][52] row-major (26624 B)
// phase2: s_h[128][132] (67584 B, overlays s_p) | s_dx[128][16] (8192 B)
#define UPD_SMEM 75776

__global__ void __launch_bounds__(256, 2) k_upd(
    const float* __restrict__ xext, int use_ext, int psel,
    const float* __restrict__ f0w, const float* __restrict__ f0b,
    const float* __restrict__ f1w,
    float* __restrict__ upd_slot, int rsel, uint32_t key0, uint32_t key1)
{
    extern __shared__ float sm[];
    int t = threadIdx.x;
    const float* __restrict__ gp = g_perc[psel];
    int P0 = (int)blockIdx.x * 128;

    float* s_p  = sm;                   // [128][52] during phase 1 (row-major)
    float* s_h  = sm;                   // [128][132] phase 2 (overlays s_p)
    float* s_dx = sm + 16896;           // [128][16]

    for (int i = t; i < 1536; i += 256) {          // 128 pix * 12 c4-groups
        int pix = i / 12, c4 = (i - pix * 12) * 4;
        float4 v = *(const float4*)&gp[(P0 + pix) * 48 + c4];
        *(float4*)&s_p[pix * 52 + c4] = v;
    }
    __syncthreads();

    // GEMM1: h[128 pix][128 e] = perc[128][48] @ f0[48][128] + b, relu (8x8 tile)
    int tx = t & 15, ty = t >> 4;
    int e0 = tx * 8, p0 = ty * 8;
    float acc[8][8];
#pragma unroll
    for (int j = 0; j < 8; j++) {
        float bj = __ldg(&f0b[e0 + j]);
#pragma unroll
        for (int i = 0; i < 8; i++) acc[i][j] = bj;
    }

#pragma unroll 3
    for (int k4 = 0; k4 < 12; k4++) {
        float4 pv[8];
#pragma unroll
        for (int i = 0; i < 8; i++)
            pv[i] = *(const float4*)&s_p[(p0 + i) * 52 + k4 * 4];
#pragma unroll
        for (int kk = 0; kk < 4; kk++) {
            int k = k4 * 4 + kk;
            float4 wa = __ldg((const float4*)&f0w[k * 128 + e0]);
            float4 wb = __ldg((const float4*)&f0w[k * 128 + e0 + 4]);
            float wr[8] = {wa.x, wa.y, wa.z, wa.w, wb.x, wb.y, wb.z, wb.w};
            float pr[8];
#pragma unroll
            for (int i = 0; i < 8; i++)
                pr[i] = (kk == 0) ? pv[i].x : (kk == 1) ? pv[i].y
                      : (kk == 2) ? pv[i].z : pv[i].w;
#pragma unroll
            for (int i = 0; i < 8; i++)
#pragma unroll
                for (int j = 0; j < 8; j++)
                    acc[i][j] = fmaf(pr[i], wr[j], acc[i][j]);
        }
    }
    __syncthreads();   // all s_p reads done before s_h overlays it

#pragma unroll
    for (int i = 0; i < 8; i++) {
        float4 ha = make_float4(fmaxf(acc[i][0], 0.f), fmaxf(acc[i][1], 0.f),
                                fmaxf(acc[i][2], 0.f), fmaxf(acc[i][3], 0.f));
        float4 hb = make_float4(fmaxf(acc[i][4], 0.f), fmaxf(acc[i][5], 0.f),
                                fmaxf(acc[i][6], 0.f), fmaxf(acc[i][7], 0.f));
        *(float4*)&s_h[(p0 + i) * 132 + e0]     = ha;
        *(float4*)&s_h[(p0 + i) * 132 + e0 + 4] = hb;
    }
    __syncthreads();

    // GEMM2: dx[128][16] = h[128][128] @ f1[128][16]; thread: 1 pix x 8 outs
    {
        int pix = t >> 1, oo = (t & 1) * 8;
        float d[8];
#pragma unroll
        for (int j = 0; j < 8; j++) d[j] = 0.f;
#pragma unroll 4
        for (int k4 = 0; k4 < 32; k4++) {
            float4 hv4 = *(const float4*)&s_h[pix * 132 + k4 * 4];
            float hr[4] = {hv4.x, hv4.y, hv4.z, hv4.w};
#pragma unroll
            for (int kk = 0; kk < 4; kk++) {
                int k = k4 * 4 + kk;
                float4 w0 = __ldg((const float4*)&f1w[k * 16 + oo]);
                float4 w1 = __ldg((const float4*)&f1w[k * 16 + oo + 4]);
                float hv = hr[kk];
                d[0] = fmaf(hv, w0.x, d[0]);
                d[1] = fmaf(hv, w0.y, d[1]);
                d[2] = fmaf(hv, w0.z, d[2]);
                d[3] = fmaf(hv, w0.w, d[3]);
                d[4] = fmaf(hv, w1.x, d[4]);
                d[5] = fmaf(hv, w1.y, d[5]);
                d[6] = fmaf(hv, w1.z, d[6]);
                d[7] = fmaf(hv, w1.w, d[7]);
            }
        }
        *(float4*)&s_dx[pix * 16 + oo]     = make_float4(d[0], d[1], d[2], d[3]);
        *(float4*)&s_dx[pix * 16 + oo + 4] = make_float4(d[4], d[5], d[6], d[7]);
    }
    __syncthreads();

    if (t < 128) {
        const float* __restrict__ x = use_ext ? xext : g_xcur;
        int gp2 = P0 + t;
        uint2 r = d_threefry(key0, key1, 0u, (uint32_t)gp2);
        uint32_t bits = r.x ^ r.y;
        float u = __uint_as_float((bits >> 9) | 0x3f800000u) - 1.0f;
        float lam = g_lam[rsel * NPIX + gp2];
        float updf = (u < lam) ? 0.0f : 1.0f;

        int b = gp2 / 5184; int hw = gp2 - b * 5184;
        int h = hw / 72, w = hw - h * 72;
        float m = -3.4e38f;
#pragma unroll
        for (int i = 0; i < 3; i++) {
            int hh = h + i - 1;
            if ((unsigned)hh >= 72u) continue;
#pragma unroll
            for (int j = 0; j < 3; j++) {
                int ww = w + j - 1;
                if ((unsigned)ww >= 72u) continue;
                m = fmaxf(m, x[((b * 5184 + hh * 72 + ww) << 4) + 3]);
            }
        }
        g_pre[gp2] = (m > 0.1f) ? 1.f : 0.f;
        upd_slot[gp2] = updf;

        const float4* __restrict__ xr = (const float4*)(x + (gp2 << 4));
        float4* __restrict__ xo = (float4*)(g_xn + (gp2 << 4));
#pragma unroll
        for (int q = 0; q < 4; q++) {
            float4 xv = xr[q];
            float4 dv = *(const float4*)&s_dx[t * 16 + q * 4];
            xv.x = fmaf(dv.x, updf, xv.x);
            xv.y = fmaf(dv.y, updf, xv.y);
            xv.z = fmaf(dv.z, updf, xv.z);
            xv.w = fmaf(dv.w, updf, xv.w);
            xo[q] = xv;
        }
    }
}

// ---------------- conv2 + lambda/p/un bookkeeping (162 blocks) ----------------
__global__ void k_c2(const float* __restrict__ w2, const float* __restrict__ b2,
                     float* __restrict__ lam_slot, float* __restrict__ p_slot,
                     int wsel, int is_first)
{
    __shared__ float ws[144];
    if (threadIdx.x < 144) ws[threadIdx.x] = w2[threadIdx.x];
    __syncthreads();

    int p = blockIdx.x * 256 + threadIdx.x;
    int b = p / 5184; int hw = p - b * 5184;
    int h = hw / 72, w = hw - h * 72;

    float acc = b2[0];
#pragma unroll
    for (int i = 0; i < 3; i++) {
        int hh = h + i - 1;
        if ((unsigned)hh >= 72u) continue;
#pragma unroll
        for (int j = 0; j < 3; j++) {
            int ww = w + j - 1;
            if ((unsigned)ww >= 72u) continue;
            const float4* __restrict__ hp =
                (const float4*)&g_h[(b * 5184 + hh * 72 + ww) << 4];
            const float* __restrict__ wp = ws + (i * 3 + j) * 16;
#pragma unroll
            for (int q = 0; q < 4; q++) {
                float4 hv = hp[q];
                acc = fmaf(hv.x, wp[q * 4 + 0], acc);
                acc = fmaf(hv.y, wp[q * 4 + 1], acc);
                acc = fmaf(hv.z, wp[q * 4 + 2], acc);
                acc = fmaf(hv.w, wp[q * 4 + 3], acc);
            }
        }
    }
    float lam = 1.f / (1.f + expf(-acc));
    g_lam[wsel * NPIX + p] = lam;
    float un = is_first ? 1.0f : g_un[p];
    lam_slot[p] = lam;
    p_slot[p] = un * lam + 1e-6f;
    g_un[p] = un * (1.f - lam);
}

// ---------------- life mask + x_steps emit (162 blocks) ----------------
__global__ void k_life(float* __restrict__ xsteps_slot)
{
    int p = blockIdx.x * 256 + threadIdx.x;
    int b = p / 5184; int hw = p - b * 5184;
    int h = hw / 72, w = hw - h * 72;
    float m = -3.4e38f;
#pragma unroll
    for (int i = 0; i < 3; i++) {
        int hh = h + i - 1;
        if ((unsigned)hh >= 72u) continue;
#pragma unroll
        for (int j = 0; j < 3; j++) {
            int ww = w + j - 1;
            if ((unsigned)ww >= 72u) continue;
            m = fmaxf(m, g_xn[((b * 5184 + hh * 72 + ww) << 4) + 3]);
        }
    }
    float life = ((m > 0.1f) && (g_pre[p] != 0.f)) ? 1.f : 0.f;
    const float4* __restrict__ xi = (const float4*)(g_xn + (p << 4));
    float4* __restrict__ xc = (float4*)(g_xcur + (p << 4));
    float4* __restrict__ xs = (float4*)(xsteps_slot + (p << 4));
#pragma unroll
    for (int q = 0; q < 4; q++) {
        float4 v = xi[q];
        v.x *= life; v.y *= life; v.z *= life; v.w *= life;
        xc[q] = v;
        xs[q] = v;
    }
}

// ------- normalize p over the T axis (in-place in output region) -------
__global__ void k_pnorm(float* __restrict__ pbase) {
    int p = blockIdx.x * 256 + threadIdx.x;
    float s = 0.f;
#pragma unroll 8
    for (int t = 0; t < TT; t++) s += pbase[t * NPIX + p];
#pragma unroll 8
    for (int t = 0; t < TT; t++) pbase[t * NPIX + p] = pbase[t * NPIX + p] / s;
}

// ---------------- launch ----------------
extern "C" void kernel_launch(void* const* d_in, const int* in_sizes, int n_in,
                              void* d_out, int out_size) {
    (void)in_sizes; (void)n_in; (void)out_size;
    const float* x   = (const float*)d_in[0];
    const float* c1w = (const float*)d_in[1];
    const float* c1b = (const float*)d_in[2];
    const float* c2w = (const float*)d_in[3];
    const float* c2b = (const float*)d_in[4];
    const float* f0w = (const float*)d_in[5];
    const float* f0b = (const float*)d_in[6];
    const float* f1w = (const float*)d_in[7];

    float* out    = (float*)d_out;
    float* xsteps = out;                                  // (64, NPIX, 16)
    float* pout   = out + (size_t)TT * NPIX * 16;         // (64, NPIX)
    float* lamout = pout + (size_t)TT * NPIX;             // (64, NPIX)
    float* updout = lamout + (size_t)TT * NPIX;           // (64, NPIX)

    static cudaStream_t sB;
    static cudaEvent_t evA, evB;
    static int inited = 0;
    if (!inited) {
        cudaFuncSetAttribute(k_c1,  cudaFuncAttributeMaxDynamicSharedMemorySize, C1_SMEM);
        cudaFuncSetAttribute(k_upd, cudaFuncAttributeMaxDynamicSharedMemorySize, UPD_SMEM);
        cudaStreamCreateWithFlags(&sB, cudaStreamNonBlocking);
        cudaEventCreateWithFlags(&evA, cudaEventDisableTiming);
        cudaEventCreateWithFlags(&evB, cudaEventDisableTiming);
        inited = 1;
    }

    // per-step keys: fold_in(key(42), k) = threefry((0,42),(0,k))
    uint32_t kk0[TT], kk1[TT];
    for (int n = 0; n < TT; n++) h_threefry(0u, 42u, 0u, (uint32_t)n, &kk0[n], &kk1[n]);

    // ---- step 0: update depends on THIS step's lambda -> strict serial order ----
    k_perc<<<648, 256>>>(x, 1, 0);
    k_c1<<<192, 256, C1_SMEM>>>(0, c1w, c1b);
    k_c2<<<162, 256>>>(c2w, c2b, lamout, pout, 0, 1);
    k_upd<<<324, 256, UPD_SMEM>>>(x, 1, 0, f0w, f0b, f1w, updout, 0, kk0[0], kk1[0]);
    k_life<<<162, 256>>>(xsteps);

    // ---- steps 1..63: (c1 -> c2) side chain overlapped on stream sB ----
    for (int k = 1; k < TT; k++) {
        int wsel = k & 1;
        int rsel = (k - 1) & 1;
        int psel = k & 1;

        // main chain: perc_k (after life_{k-1} by stream order)
        k_perc<<<648, 256>>>(x, 0, psel);
        cudaEventRecord(evA, 0);
        cudaStreamWaitEvent(sB, evA, 0);

        // main chain must wait on c2_{k-1} (lambda slot rsel) — wait BEFORE
        // re-recording evB below so it references the previous record.
        if (k >= 2) cudaStreamWaitEvent(0, evB, 0);

        // side chain: c1_k -> c2_k on sB
        k_c1<<<192, 256, C1_SMEM, sB>>>(psel, c1w, c1b);
        k_c2<<<162, 256, 0, sB>>>(c2w, c2b,
                                  lamout + (size_t)k * NPIX, pout + (size_t)k * NPIX,
                                  wsel, 0);
        cudaEventRecord(evB, sB);

        // main chain: upd_k -> life_k
        k_upd<<<324, 256, UPD_SMEM>>>(x, 0, psel, f0w, f0b, f1w,
                                      updout + (size_t)k * NPIX, rsel, kk0[k], kk1[k]);
        k_life<<<162, 256>>>(xsteps + (size_t)k * NPIX * 16);
    }

    // join side chain (c2_63 writes pout[63]) before normalization
    cudaStreamWaitEvent(0, evB, 0);
    k_pnorm<<<162, 256>>>(pout);
}